// round 5
// baseline (speedup 1.0000x reference)
#include <cuda_runtime.h>
#include <cuda_fp16.h>
#include <cstdint>

#define B_ROWS   8192
#define LAT      64
#define COND     256
#define OUT_DIM  512
#define HID      1024
#define NEXP     8
#define GH       128
#define INPUT_D  320
#define INTER_D  1088
#define KT0      (NEXP * INPUT_D)   // 2560
#define KT1      (NEXP * INTER_D)   // 8704

// ---------------- scratch (device globals; no allocs allowed) ----------------
__device__ float  g_coeff[B_ROWS * NEXP];
__device__ float  g_x[B_ROWS * INTER_D];       // LN output (fp32, compact)
__device__ float  g_hA[B_ROWS * HID];
__device__ float  g_hB[B_ROWS * HID];
__device__ __half g_w16_0[(size_t)HID * KT0];
__device__ __half g_w16_1[(size_t)HID * KT1];
__device__ __half g_w16_2[(size_t)HID * KT1];
__device__ __half g_w16_3[(size_t)OUT_DIM * KT1];

// ---------------- helpers ----------------
__device__ __forceinline__ float elu1(float v) { return v > 0.f ? v : expm1f(v); }

__device__ __forceinline__ uint32_t smem_u32(const void* p) {
    uint32_t a;
    asm("{ .reg .u64 t; cvta.to.shared.u64 t, %1; cvt.u32.u64 %0, t; }" : "=r"(a) : "l"(p));
    return a;
}
__device__ __forceinline__ void cp_async16(uint32_t dst, const void* src) {
    asm volatile("cp.async.cg.shared.global [%0], [%1], 16;" :: "r"(dst), "l"(src) : "memory");
}
__device__ __forceinline__ void cp_commit() {
    asm volatile("cp.async.commit_group;" ::: "memory");
}
__device__ __forceinline__ void cp_wait2() {
    asm volatile("cp.async.wait_group 2;" ::: "memory");
}
__device__ __forceinline__ void sts128h(uint32_t a, const __half2 h[4]) {
    asm volatile("st.shared.v4.b32 [%0], {%1,%2,%3,%4};" ::
                 "r"(a),
                 "r"(*(const uint32_t*)&h[0]), "r"(*(const uint32_t*)&h[1]),
                 "r"(*(const uint32_t*)&h[2]), "r"(*(const uint32_t*)&h[3]) : "memory");
}
__device__ __forceinline__ void ldsm4(uint32_t r[4], uint32_t addr) {
    asm volatile("ldmatrix.sync.aligned.m8n8.x4.shared.b16 {%0,%1,%2,%3}, [%4];"
                 : "=r"(r[0]), "=r"(r[1]), "=r"(r[2]), "=r"(r[3]) : "r"(addr));
}
__device__ __forceinline__ void mma_f16(float c[4], const uint32_t a[4],
                                        uint32_t b0, uint32_t b1) {
    asm volatile(
        "mma.sync.aligned.m16n8k16.row.col.f32.f16.f16.f32 "
        "{%0,%1,%2,%3}, {%4,%5,%6,%7}, {%8,%9}, {%0,%1,%2,%3};"
        : "+f"(c[0]), "+f"(c[1]), "+f"(c[2]), "+f"(c[3])
        : "r"(a[0]), "r"(a[1]), "r"(a[2]), "r"(a[3]), "r"(b0), "r"(b1));
}

// ---------------- weight permute: Wt[n][j*8+e] = fp16(W[e][j][n]) ----------------
__global__ __launch_bounds__(256)
void permute_w(const float* __restrict__ W, __half* __restrict__ Wt, int J, int N) {
    const int n = blockIdx.x * 32 + threadIdx.x;
    const int j = blockIdx.y * 8 + threadIdx.y;
    const int KT = NEXP * J;
    __half2 v[4];
    #pragma unroll
    for (int e = 0; e < 4; e++) {
        float lo = W[((size_t)(2 * e) * J + j) * N + n];
        float hi = W[((size_t)(2 * e + 1) * J + j) * N + n];
        v[e] = __floats2half2_rn(lo, hi);
    }
    *(uint4*)(Wt + (size_t)n * KT + j * 8) = *(const uint4*)v;
}

// ---------------- gate MLP + softmax -> coeff [B, 8] ----------------
__global__ __launch_bounds__(128)
void gate_kernel(const float* __restrict__ z, const float* __restrict__ c,
                 const float* __restrict__ g0w, const float* __restrict__ g0b,
                 const float* __restrict__ g1w, const float* __restrict__ g1b,
                 const float* __restrict__ g2w, const float* __restrict__ g2b,
                 float* __restrict__ coeff) {
    __shared__ float xs[8][INPUT_D];
    __shared__ float h1[8][GH];
    __shared__ float h2[8][GH];
    __shared__ float lg[8][NEXP];
    const int row0 = blockIdx.x * 8;
    const int t = threadIdx.x;

    for (int idx = t; idx < 8 * INPUT_D; idx += 128) {
        int r = idx / INPUT_D, j = idx % INPUT_D;
        xs[r][j] = (j < LAT) ? z[(row0 + r) * LAT + j]
                             : c[(row0 + r) * COND + (j - LAT)];
    }
    __syncthreads();
    {
        float acc[8];
        float b0 = g0b[t];
        #pragma unroll
        for (int r = 0; r < 8; r++) acc[r] = b0;
        for (int j = 0; j < INPUT_D; j++) {
            float wv = g0w[j * GH + t];
            #pragma unroll
            for (int r = 0; r < 8; r++) acc[r] = fmaf(xs[r][j], wv, acc[r]);
        }
        #pragma unroll
        for (int r = 0; r < 8; r++) h1[r][t] = elu1(acc[r]);
    }
    __syncthreads();
    {
        float acc[8];
        float b1 = g1b[t];
        #pragma unroll
        for (int r = 0; r < 8; r++) acc[r] = b1;
        for (int j = 0; j < GH; j++) {
            float wv = g1w[j * GH + t];
            #pragma unroll
            for (int r = 0; r < 8; r++) acc[r] = fmaf(h1[r][j], wv, acc[r]);
        }
        #pragma unroll
        for (int r = 0; r < 8; r++) h2[r][t] = elu1(acc[r]);
    }
    __syncthreads();
    if (t < 64) {
        int r = t >> 3, e = t & 7;
        float acc = g2b[e];
        for (int j = 0; j < GH; j++) acc = fmaf(h2[r][j], g2w[j * NEXP + e], acc);
        lg[r][e] = acc;
    }
    __syncthreads();
    if (t < 8) {
        float m = -1e30f;
        #pragma unroll
        for (int e = 0; e < NEXP; e++) m = fmaxf(m, lg[t][e]);
        float ex[NEXP], s = 0.f;
        #pragma unroll
        for (int e = 0; e < NEXP; e++) { ex[e] = expf(lg[t][e] - m); s += ex[e]; }
        float inv = 1.f / s;
        #pragma unroll
        for (int e = 0; e < NEXP; e++) coeff[(row0 + t) * NEXP + e] = ex[e] * inv;
    }
}

// ---------------- LN(concat(z, src)) warp-per-row -> fp32 x ----------------
template<int SRC>
__global__ __launch_bounds__(256)
void ln_concat_warp(const float* __restrict__ z, const float* __restrict__ src,
                    float* __restrict__ out) {
    constexpr int J = LAT + SRC;
    constexpr int N4 = J / 4;
    constexpr int NIT = (N4 + 31) / 32;
    const int row = blockIdx.x * 8 + (threadIdx.x >> 5);
    const int lane = threadIdx.x & 31;
    const float4* z4 = (const float4*)(z + (size_t)row * LAT);
    const float4* s4 = (const float4*)(src + (size_t)row * SRC);

    float4 v[NIT];
    float s = 0.f, ss = 0.f;
    #pragma unroll
    for (int k = 0; k < NIT; k++) {
        int i = lane + k * 32;
        if (i < N4) {
            float4 t = (i < LAT / 4) ? z4[i] : s4[i - LAT / 4];
            v[k] = t;
            s += t.x + t.y + t.z + t.w;
            ss += t.x * t.x + t.y * t.y + t.z * t.z + t.w * t.w;
        }
    }
    #pragma unroll
    for (int o = 16; o > 0; o >>= 1) {
        s  += __shfl_xor_sync(0xffffffffu, s, o);
        ss += __shfl_xor_sync(0xffffffffu, ss, o);
    }
    const float mean = s / (float)J;
    const float var = ss / (float)J - mean * mean;
    const float rstd = rsqrtf(var + 1e-5f);
    float4* o4 = (float4*)(out + (size_t)row * J);
    #pragma unroll
    for (int k = 0; k < NIT; k++) {
        int i = lane + k * 32;
        if (i < N4) {
            float4 t = v[k];
            t.x = (t.x - mean) * rstd; t.y = (t.y - mean) * rstd;
            t.z = (t.z - mean) * rstd; t.w = (t.w - mean) * rstd;
            o4[i] = t;
        }
    }
}

// ---------------- pipelined fp16 HMMA GEMM with on-the-fly A expansion --------
// A[b][ (kt*8+jl)*8+e ] = fp16(coeff[b,e] * x[b, kt*8+jl]) built in smem.
// BM=128, BN=256, BK=64(halves), B: 4 cp.async stages; A: 2 STS buffers.
// 256 threads = 8 warps (2m x 4n), warp tile 64x64.
#define A_BUF_BYTES 16384
#define B_STG_BYTES 32768
#define GEMM_SMEM   (2 * A_BUF_BYTES + 4 * B_STG_BYTES)

template<int J, int NTOT, bool ACT>
__global__ __launch_bounds__(256, 1)
void moe_gemm_h(const float* __restrict__ x, const float* __restrict__ coeff,
                const __half* __restrict__ Wt, const float* __restrict__ bias,
                float* __restrict__ out) {
    constexpr int KTOT = NEXP * J;
    constexpr int NKT = KTOT / 64;
    extern __shared__ char smem[];
    const uint32_t sbase = smem_u32(smem);
    const uint32_t bBase = sbase + 2 * A_BUF_BYTES;

    const int tid = threadIdx.x;
    const int lane = tid & 31;
    const int wid = tid >> 5;
    const int warpM = wid >> 2;          // 0..1 -> m offset 64
    const int warpN = wid & 3;           // 0..3 -> n offset 64
    const int bm = blockIdx.y * 128;
    const int bn = blockIdx.x * 256;

    const __half* Bg = Wt + (size_t)bn * KTOT;

    // ---- A expansion state: thread owns tile row (tid>>1), 4 j-chunks ----
    const int rowA = tid >> 1;
    const int cq = (tid & 1) * 4;        // first chunk (j_local) handled
    const float* xrow = x + (size_t)(bm + rowA) * J + cq;
    float cf[NEXP];
    {
        const float4 c0 = *(const float4*)(coeff + (size_t)(bm + rowA) * NEXP);
        const float4 c1 = *(const float4*)(coeff + (size_t)(bm + rowA) * NEXP + 4);
        cf[0] = c0.x; cf[1] = c0.y; cf[2] = c0.z; cf[3] = c0.w;
        cf[4] = c1.x; cf[5] = c1.y; cf[6] = c1.z; cf[7] = c1.w;
    }
    const uint32_t aRowBase = sbase + rowA * 128;

    auto fillA = [&](int buf, const float4& xr) {
        const float xv[4] = { xr.x, xr.y, xr.z, xr.w };
        #pragma unroll
        for (int q = 0; q < 4; q++) {
            const int ch = cq + q;
            __half2 h[4];
            #pragma unroll
            for (int e = 0; e < 4; e++)
                h[e] = __floats2half2_rn(xv[q] * cf[2 * e], xv[q] * cf[2 * e + 1]);
            sts128h(aRowBase + buf * A_BUF_BYTES + ((ch ^ (rowA & 7)) << 4), h);
        }
    };
    auto fetchB = [&](int kt, int s) {
        const uint32_t bS = bBase + s * B_STG_BYTES;
        #pragma unroll
        for (int i = 0; i < 8; i++) {
            const int idx = tid + i * 256;       // 0..2047
            const int row = idx >> 3;
            const int ch = idx & 7;
            cp_async16(bS + row * 128 + ((ch ^ (row & 7)) << 4),
                       Bg + (size_t)row * KTOT + kt * 64 + ch * 8);
        }
    };

    float acc[4][8][4];
    #pragma unroll
    for (int mf = 0; mf < 4; mf++)
        #pragma unroll
        for (int nf = 0; nf < 8; nf++)
            #pragma unroll
            for (int q = 0; q < 4; q++) acc[mf][nf][q] = 0.f;

    // ---- prologue ----
    float4 xr = *(const float4*)(xrow);          // x for kt=0
    fillA(0, xr);
    xr = *(const float4*)(xrow + 8);             // x for kt=1
    fetchB(0, 0); cp_commit();
    fetchB(1, 1); cp_commit();

    const int lr = lane & 15;
    const int lc = lane >> 4;

    for (int kt = 0; kt < NKT; kt++) {
        if (kt + 2 < NKT) fetchB(kt + 2, (kt + 2) & 3);
        cp_commit();
        cp_wait2();
        __syncthreads();

        if (kt + 1 < NKT) fillA((kt + 1) & 1, xr);
        if (kt + 2 < NKT) xr = *(const float4*)(xrow + (kt + 2) * 8);

        const uint32_t aS = sbase + (kt & 1) * A_BUF_BYTES;
        const uint32_t bS = bBase + (kt & 3) * B_STG_BYTES;
        #pragma unroll
        for (int ks = 0; ks < 4; ks++) {
            const int chunk = ks * 2 + lc;
            uint32_t aF[4][4];
            #pragma unroll
            for (int mf = 0; mf < 4; mf++) {
                const int r = warpM * 64 + mf * 16 + lr;
                ldsm4(aF[mf], aS + r * 128 + ((chunk ^ (r & 7)) << 4));
            }
            uint32_t bF[4][4];
            #pragma unroll
            for (int nf2 = 0; nf2 < 4; nf2++) {
                const int r = warpN * 64 + nf2 * 16 + lr;
                ldsm4(bF[nf2], bS + r * 128 + ((chunk ^ (r & 7)) << 4));
            }
            #pragma unroll
            for (int mf = 0; mf < 4; mf++)
                #pragma unroll
                for (int nf = 0; nf < 8; nf++)
                    mma_f16(acc[mf][nf], aF[mf], bF[nf >> 1][nf & 1], bF[nf >> 1][(nf & 1) + 2]);
        }
    }

    // ---- epilogue: + coeff@bias, optional elu, store ----
    #pragma unroll
    for (int mf = 0; mf < 4; mf++) {
        const int r0 = bm + warpM * 64 + mf * 16 + (lane >> 2);
        const int r1 = r0 + 8;
        float cf0[NEXP], cf1[NEXP];
        #pragma unroll
        for (int e = 0; e < NEXP; e++) {
            cf0[e] = __ldg(&coeff[r0 * NEXP + e]);
            cf1[e] = __ldg(&coeff[r1 * NEXP + e]);
        }
        #pragma unroll
        for (int nf = 0; nf < 8; nf++) {
            const int col = bn + warpN * 64 + nf * 8 + (lane & 3) * 2;
            float b00 = 0.f, b01 = 0.f, b10 = 0.f, b11 = 0.f;
            #pragma unroll
            for (int e = 0; e < NEXP; e++) {
                const float be0 = __ldg(&bias[e * NTOT + col]);
                const float be1 = __ldg(&bias[e * NTOT + col + 1]);
                b00 = fmaf(cf0[e], be0, b00); b01 = fmaf(cf0[e], be1, b01);
                b10 = fmaf(cf1[e], be0, b10); b11 = fmaf(cf1[e], be1, b11);
            }
            float v00 = acc[mf][nf][0] + b00;
            float v01 = acc[mf][nf][1] + b01;
            float v10 = acc[mf][nf][2] + b10;
            float v11 = acc[mf][nf][3] + b11;
            if (ACT) { v00 = elu1(v00); v01 = elu1(v01); v10 = elu1(v10); v11 = elu1(v11); }
            *(float2*)(&out[(size_t)r0 * NTOT + col]) = make_float2(v00, v01);
            *(float2*)(&out[(size_t)r1 * NTOT + col]) = make_float2(v10, v11);
        }
    }
}

// ---------------- host launcher ----------------
extern "C" void kernel_launch(void* const* d_in, const int* in_sizes, int n_in,
                              void* d_out, int out_size) {
    const float* z   = (const float*)d_in[0];
    const float* c   = (const float*)d_in[1];
    const float* g0w = (const float*)d_in[2];
    const float* g0b = (const float*)d_in[3];
    const float* g1w = (const float*)d_in[4];
    const float* g1b = (const float*)d_in[5];
    const float* g2w = (const float*)d_in[6];
    const float* g2b = (const float*)d_in[7];
    const float* w0  = (const float*)d_in[8];
    const float* b0  = (const float*)d_in[9];
    const float* w1  = (const float*)d_in[10];
    const float* b1  = (const float*)d_in[11];
    const float* w2  = (const float*)d_in[12];
    const float* b2  = (const float*)d_in[13];
    const float* w3  = (const float*)d_in[14];
    const float* b3  = (const float*)d_in[15];

    float *coeff, *x, *hA, *hB;
    __half *w16_0, *w16_1, *w16_2, *w16_3;
    cudaGetSymbolAddress((void**)&coeff, g_coeff);
    cudaGetSymbolAddress((void**)&x, g_x);
    cudaGetSymbolAddress((void**)&hA, g_hA);
    cudaGetSymbolAddress((void**)&hB, g_hB);
    cudaGetSymbolAddress((void**)&w16_0, g_w16_0);
    cudaGetSymbolAddress((void**)&w16_1, g_w16_1);
    cudaGetSymbolAddress((void**)&w16_2, g_w16_2);
    cudaGetSymbolAddress((void**)&w16_3, g_w16_3);

    cudaFuncSetAttribute(moe_gemm_h<INPUT_D, HID, true>,
                         cudaFuncAttributeMaxDynamicSharedMemorySize, GEMM_SMEM);
    cudaFuncSetAttribute(moe_gemm_h<INTER_D, HID, true>,
                         cudaFuncAttributeMaxDynamicSharedMemorySize, GEMM_SMEM);
    cudaFuncSetAttribute(moe_gemm_h<INTER_D, OUT_DIM, false>,
                         cudaFuncAttributeMaxDynamicSharedMemorySize, GEMM_SMEM);

    permute_w<<<dim3(HID / 32, INPUT_D / 8), dim3(32, 8)>>>(w0, w16_0, INPUT_D, HID);
    permute_w<<<dim3(HID / 32, INTER_D / 8), dim3(32, 8)>>>(w1, w16_1, INTER_D, HID);
    permute_w<<<dim3(HID / 32, INTER_D / 8), dim3(32, 8)>>>(w2, w16_2, INTER_D, HID);
    permute_w<<<dim3(OUT_DIM / 32, INTER_D / 8), dim3(32, 8)>>>(w3, w16_3, INTER_D, OUT_DIM);

    gate_kernel<<<B_ROWS / 8, 128>>>(z, c, g0w, g0b, g1w, g1b, g2w, g2b, coeff);

    // layer 0
    ln_concat_warp<COND><<<B_ROWS / 8, 256>>>(z, c, x);
    moe_gemm_h<INPUT_D, HID, true><<<dim3(HID / 256, B_ROWS / 128), 256, GEMM_SMEM>>>(
        x, coeff, w16_0, b0, hA);
    // layer 1
    ln_concat_warp<HID><<<B_ROWS / 8, 256>>>(z, hA, x);
    moe_gemm_h<INTER_D, HID, true><<<dim3(HID / 256, B_ROWS / 128), 256, GEMM_SMEM>>>(
        x, coeff, w16_1, b1, hB);
    // layer 2
    ln_concat_warp<HID><<<B_ROWS / 8, 256>>>(z, hB, x);
    moe_gemm_h<INTER_D, HID, true><<<dim3(HID / 256, B_ROWS / 128), 256, GEMM_SMEM>>>(
        x, coeff, w16_2, b2, hA);
    // layer 3 (no activation) -> d_out
    ln_concat_warp<HID><<<B_ROWS / 8, 256>>>(z, hA, x);
    moe_gemm_h<INTER_D, OUT_DIM, false><<<dim3(OUT_DIM / 256, B_ROWS / 128), 256, GEMM_SMEM>>>(
        x, coeff, w16_3, b3, (float*)d_out);
}

// round 6
// speedup vs baseline: 1.0252x; 1.0252x over previous
#include <cuda_runtime.h>
#include <cuda_fp16.h>
#include <cstdint>

#define B_ROWS   8192
#define LAT      64
#define COND     256
#define OUT_DIM  512
#define HID      1024
#define NEXP     8
#define GH       128
#define INPUT_D  320
#define INTER_D  1088
#define KT0      (NEXP * INPUT_D)   // 2560
#define KT1      (NEXP * INTER_D)   // 8704

// ---------------- scratch (device globals; no allocs allowed) ----------------
__device__ float  g_coeff[B_ROWS * NEXP];
__device__ float  g_hA[B_ROWS * HID];
__device__ float  g_hB[B_ROWS * HID];
__device__ __half g_a16[(size_t)B_ROWS * KT1];
__device__ __half g_w16_0[(size_t)HID * KT0];
__device__ __half g_w16_1[(size_t)HID * KT1];
__device__ __half g_w16_2[(size_t)HID * KT1];
__device__ __half g_w16_3[(size_t)OUT_DIM * KT1];

// ---------------- helpers ----------------
__device__ __forceinline__ float elu1(float v) { return v > 0.f ? v : expm1f(v); }

__device__ __forceinline__ uint32_t smem_u32(const void* p) {
    uint32_t a;
    asm("{ .reg .u64 t; cvta.to.shared.u64 t, %1; cvt.u32.u64 %0, t; }" : "=r"(a) : "l"(p));
    return a;
}
__device__ __forceinline__ void cp_async16(uint32_t dst, const void* src) {
    asm volatile("cp.async.cg.shared.global [%0], [%1], 16;" :: "r"(dst), "l"(src) : "memory");
}
__device__ __forceinline__ void cp_commit() {
    asm volatile("cp.async.commit_group;" ::: "memory");
}
__device__ __forceinline__ void cp_wait1() {
    asm volatile("cp.async.wait_group 1;" ::: "memory");
}
__device__ __forceinline__ void ldsm4(uint32_t r[4], uint32_t addr) {
    asm volatile("ldmatrix.sync.aligned.m8n8.x4.shared.b16 {%0,%1,%2,%3}, [%4];"
                 : "=r"(r[0]), "=r"(r[1]), "=r"(r[2]), "=r"(r[3]) : "r"(addr));
}
__device__ __forceinline__ void mma_f16(float c[4], const uint32_t a[4],
                                        uint32_t b0, uint32_t b1) {
    asm volatile(
        "mma.sync.aligned.m16n8k16.row.col.f32.f16.f16.f32 "
        "{%0,%1,%2,%3}, {%4,%5,%6,%7}, {%8,%9}, {%0,%1,%2,%3};"
        : "+f"(c[0]), "+f"(c[1]), "+f"(c[2]), "+f"(c[3])
        : "r"(a[0]), "r"(a[1]), "r"(a[2]), "r"(a[3]), "r"(b0), "r"(b1));
}

// ---------------- weight permute: Wt[n][j*8+e] = fp16(W[e][j][n]) ----------------
__global__ __launch_bounds__(256)
void permute_w(const float* __restrict__ W, __half* __restrict__ Wt, int J, int N) {
    const int n = blockIdx.x * 32 + threadIdx.x;
    const int j = blockIdx.y * 8 + threadIdx.y;
    const int KT = NEXP * J;
    __half2 v[4];
    #pragma unroll
    for (int e = 0; e < 4; e++) {
        float lo = W[((size_t)(2 * e) * J + j) * N + n];
        float hi = W[((size_t)(2 * e + 1) * J + j) * N + n];
        v[e] = __floats2half2_rn(lo, hi);
    }
    *(uint4*)(Wt + (size_t)n * KT + j * 8) = *(const uint4*)v;
}

// ---------------- gate MLP + softmax -> coeff [B, 8] ----------------
__global__ __launch_bounds__(128)
void gate_kernel(const float* __restrict__ z, const float* __restrict__ c,
                 const float* __restrict__ g0w, const float* __restrict__ g0b,
                 const float* __restrict__ g1w, const float* __restrict__ g1b,
                 const float* __restrict__ g2w, const float* __restrict__ g2b,
                 float* __restrict__ coeff) {
    __shared__ float xs[8][INPUT_D];
    __shared__ float h1[8][GH];
    __shared__ float h2[8][GH];
    __shared__ float lg[8][NEXP];
    const int row0 = blockIdx.x * 8;
    const int t = threadIdx.x;

    for (int idx = t; idx < 8 * INPUT_D; idx += 128) {
        int r = idx / INPUT_D, j = idx % INPUT_D;
        xs[r][j] = (j < LAT) ? z[(row0 + r) * LAT + j]
                             : c[(row0 + r) * COND + (j - LAT)];
    }
    __syncthreads();
    {
        float acc[8];
        float b0 = g0b[t];
        #pragma unroll
        for (int r = 0; r < 8; r++) acc[r] = b0;
        for (int j = 0; j < INPUT_D; j++) {
            float wv = g0w[j * GH + t];
            #pragma unroll
            for (int r = 0; r < 8; r++) acc[r] = fmaf(xs[r][j], wv, acc[r]);
        }
        #pragma unroll
        for (int r = 0; r < 8; r++) h1[r][t] = elu1(acc[r]);
    }
    __syncthreads();
    {
        float acc[8];
        float b1 = g1b[t];
        #pragma unroll
        for (int r = 0; r < 8; r++) acc[r] = b1;
        for (int j = 0; j < GH; j++) {
            float wv = g1w[j * GH + t];
            #pragma unroll
            for (int r = 0; r < 8; r++) acc[r] = fmaf(h1[r][j], wv, acc[r]);
        }
        #pragma unroll
        for (int r = 0; r < 8; r++) h2[r][t] = elu1(acc[r]);
    }
    __syncthreads();
    if (t < 64) {
        int r = t >> 3, e = t & 7;
        float acc = g2b[e];
        for (int j = 0; j < GH; j++) acc = fmaf(h2[r][j], g2w[j * NEXP + e], acc);
        lg[r][e] = acc;
    }
    __syncthreads();
    if (t < 8) {
        float m = -1e30f;
        #pragma unroll
        for (int e = 0; e < NEXP; e++) m = fmaxf(m, lg[t][e]);
        float ex[NEXP], s = 0.f;
        #pragma unroll
        for (int e = 0; e < NEXP; e++) { ex[e] = expf(lg[t][e] - m); s += ex[e]; }
        float inv = 1.f / s;
        #pragma unroll
        for (int e = 0; e < NEXP; e++) coeff[(row0 + t) * NEXP + e] = ex[e] * inv;
    }
}

// ------- fused LN(concat(z,src)) + coeff scale + fp16 pack -> A16[b][j*8+e] -------
template<int SRC>
__global__ __launch_bounds__(256)
void ln_scale_kernel(const float* __restrict__ z, const float* __restrict__ src,
                     const float* __restrict__ coeff, __half* __restrict__ A16) {
    constexpr int J = LAT + SRC;
    constexpr int NIT = (J + 31) / 32;
    const int row = blockIdx.x * 8 + (threadIdx.x >> 5);
    const int lane = threadIdx.x & 31;
    const float* zr = z + (size_t)row * LAT;
    const float* sr = src + (size_t)row * SRC;

    float v[NIT];
    float s = 0.f, ss = 0.f;
    #pragma unroll
    for (int k = 0; k < NIT; k++) {
        const int j = lane + k * 32;
        float t = (j < LAT) ? zr[j] : sr[j - LAT];
        v[k] = t;
        s += t; ss += t * t;
    }
    #pragma unroll
    for (int o = 16; o > 0; o >>= 1) {
        s  += __shfl_xor_sync(0xffffffffu, s, o);
        ss += __shfl_xor_sync(0xffffffffu, ss, o);
    }
    const float mean = s / (float)J;
    const float var = ss / (float)J - mean * mean;
    const float rstd = rsqrtf(var + 1e-5f);

    const float cown = coeff[row * NEXP + (lane & 7)];
    float cf[NEXP];
    #pragma unroll
    for (int e = 0; e < NEXP; e++) cf[e] = __shfl_sync(0xffffffffu, cown, e);

    __half* arow = A16 + (size_t)row * (NEXP * J);
    #pragma unroll
    for (int k = 0; k < NIT; k++) {
        const int j = lane + k * 32;
        const float x = (v[k] - mean) * rstd;
        __half2 h[4];
        #pragma unroll
        for (int e = 0; e < 4; e++)
            h[e] = __floats2half2_rn(x * cf[2 * e], x * cf[2 * e + 1]);
        *(uint4*)(arow + j * 8) = *(const uint4*)h;
    }
}

// ---------------- pipelined fp16 HMMA GEMM (2 CTAs/SM) ----------------
// BM=128, BN=128, BK=64(halves), 3 stages, 128 threads = 4 warps (2m x 2n), warp 64x64
#define STAGE_BYTES 32768
#define GEMM_SMEM   (3 * STAGE_BYTES)

template<int KTOT, int NTOT, bool ACT>
__global__ __launch_bounds__(128, 2)
void moe_gemm_h(const __half* __restrict__ A16, const float* __restrict__ coeff,
                const __half* __restrict__ Wt, const float* __restrict__ bias,
                float* __restrict__ out) {
    constexpr int NKT = KTOT / 64;
    extern __shared__ char smem[];
    const uint32_t sbase = smem_u32(smem);

    const int tid = threadIdx.x;
    const int lane = tid & 31;
    const int wid = tid >> 5;
    const int warpM = wid >> 1;          // 0..1 -> m offset 64
    const int warpN = wid & 1;           // 0..1 -> n offset 64
    const int bm = blockIdx.y * 128;
    const int bn = blockIdx.x * 128;

    const __half* Ag = A16 + (size_t)bm * KTOT;
    const __half* Bg = Wt + (size_t)bn * KTOT;

    auto fetch = [&](int kt, int s) {
        const uint32_t aS = sbase + s * STAGE_BYTES;
        const uint32_t bS = aS + 16384;
        #pragma unroll
        for (int i = 0; i < 8; i++) {
            const int idx = tid + i * 128;       // 0..1023
            const int row = idx >> 3;
            const int ch = idx & 7;
            const uint32_t soff = row * 128 + ((ch ^ (row & 7)) << 4);
            cp_async16(aS + soff, Ag + (size_t)row * KTOT + kt * 64 + ch * 8);
            cp_async16(bS + soff, Bg + (size_t)row * KTOT + kt * 64 + ch * 8);
        }
        cp_commit();
    };

    float acc[4][8][4];
    #pragma unroll
    for (int mf = 0; mf < 4; mf++)
        #pragma unroll
        for (int nf = 0; nf < 8; nf++)
            #pragma unroll
            for (int q = 0; q < 4; q++) acc[mf][nf][q] = 0.f;

    fetch(0, 0);
    fetch(1, 1);

    const int lr = lane & 15;
    const int lc = lane >> 4;

    int sc = 0;                          // stage holding kt
    for (int kt = 0; kt < NKT; kt++) {
        cp_wait1();                      // stage sc (kt) complete; kt+1 may be in flight
        __syncthreads();                 // RAW for stage sc; WAR for stage (kt+2)%3

        if (kt + 2 < NKT) {
            int sf = sc + 2; if (sf >= 3) sf -= 3;
            fetch(kt + 2, sf);
        }

        const uint32_t aS = sbase + sc * STAGE_BYTES;
        const uint32_t bS = aS + 16384;
        #pragma unroll
        for (int ks = 0; ks < 4; ks++) {
            const int chunk = ks * 2 + lc;
            uint32_t aF[4][4];
            #pragma unroll
            for (int mf = 0; mf < 4; mf++) {
                const int r = warpM * 64 + mf * 16 + lr;
                ldsm4(aF[mf], aS + r * 128 + ((chunk ^ (r & 7)) << 4));
            }
            uint32_t bF[4][4];
            #pragma unroll
            for (int nf2 = 0; nf2 < 4; nf2++) {
                const int r = warpN * 64 + nf2 * 16 + lr;
                ldsm4(bF[nf2], bS + r * 128 + ((chunk ^ (r & 7)) << 4));
            }
            #pragma unroll
            for (int mf = 0; mf < 4; mf++)
                #pragma unroll
                for (int nf = 0; nf < 8; nf++)
                    mma_f16(acc[mf][nf], aF[mf], bF[nf >> 1][nf & 1], bF[nf >> 1][(nf & 1) + 2]);
        }
        if (++sc == 3) sc = 0;
    }

    // ---- epilogue: + coeff@bias, optional elu, store ----
    #pragma unroll
    for (int mf = 0; mf < 4; mf++) {
        const int r0 = bm + warpM * 64 + mf * 16 + (lane >> 2);
        const int r1 = r0 + 8;
        float cf0[NEXP], cf1[NEXP];
        #pragma unroll
        for (int e = 0; e < NEXP; e++) {
            cf0[e] = __ldg(&coeff[r0 * NEXP + e]);
            cf1[e] = __ldg(&coeff[r1 * NEXP + e]);
        }
        #pragma unroll
        for (int nf = 0; nf < 8; nf++) {
            const int col = bn + warpN * 64 + nf * 8 + (lane & 3) * 2;
            float b00 = 0.f, b01 = 0.f, b10 = 0.f, b11 = 0.f;
            #pragma unroll
            for (int e = 0; e < NEXP; e++) {
                const float be0 = __ldg(&bias[e * NTOT + col]);
                const float be1 = __ldg(&bias[e * NTOT + col + 1]);
                b00 = fmaf(cf0[e], be0, b00); b01 = fmaf(cf0[e], be1, b01);
                b10 = fmaf(cf1[e], be0, b10); b11 = fmaf(cf1[e], be1, b11);
            }
            float v00 = acc[mf][nf][0] + b00;
            float v01 = acc[mf][nf][1] + b01;
            float v10 = acc[mf][nf][2] + b10;
            float v11 = acc[mf][nf][3] + b11;
            if (ACT) { v00 = elu1(v00); v01 = elu1(v01); v10 = elu1(v10); v11 = elu1(v11); }
            *(float2*)(&out[(size_t)r0 * NTOT + col]) = make_float2(v00, v01);
            *(float2*)(&out[(size_t)r1 * NTOT + col]) = make_float2(v10, v11);
        }
    }
}

// ---------------- host launcher ----------------
extern "C" void kernel_launch(void* const* d_in, const int* in_sizes, int n_in,
                              void* d_out, int out_size) {
    const float* z   = (const float*)d_in[0];
    const float* c   = (const float*)d_in[1];
    const float* g0w = (const float*)d_in[2];
    const float* g0b = (const float*)d_in[3];
    const float* g1w = (const float*)d_in[4];
    const float* g1b = (const float*)d_in[5];
    const float* g2w = (const float*)d_in[6];
    const float* g2b = (const float*)d_in[7];
    const float* w0  = (const float*)d_in[8];
    const float* b0  = (const float*)d_in[9];
    const float* w1  = (const float*)d_in[10];
    const float* b1  = (const float*)d_in[11];
    const float* w2  = (const float*)d_in[12];
    const float* b2  = (const float*)d_in[13];
    const float* w3  = (const float*)d_in[14];
    const float* b3  = (const float*)d_in[15];

    float *coeff, *hA, *hB;
    __half *a16, *w16_0, *w16_1, *w16_2, *w16_3;
    cudaGetSymbolAddress((void**)&coeff, g_coeff);
    cudaGetSymbolAddress((void**)&hA, g_hA);
    cudaGetSymbolAddress((void**)&hB, g_hB);
    cudaGetSymbolAddress((void**)&a16, g_a16);
    cudaGetSymbolAddress((void**)&w16_0, g_w16_0);
    cudaGetSymbolAddress((void**)&w16_1, g_w16_1);
    cudaGetSymbolAddress((void**)&w16_2, g_w16_2);
    cudaGetSymbolAddress((void**)&w16_3, g_w16_3);

    cudaFuncSetAttribute(moe_gemm_h<KT0, HID, true>,
                         cudaFuncAttributeMaxDynamicSharedMemorySize, GEMM_SMEM);
    cudaFuncSetAttribute(moe_gemm_h<KT1, HID, true>,
                         cudaFuncAttributeMaxDynamicSharedMemorySize, GEMM_SMEM);
    cudaFuncSetAttribute(moe_gemm_h<KT1, OUT_DIM, false>,
                         cudaFuncAttributeMaxDynamicSharedMemorySize, GEMM_SMEM);

    permute_w<<<dim3(HID / 32, INPUT_D / 8), dim3(32, 8)>>>(w0, w16_0, INPUT_D, HID);
    permute_w<<<dim3(HID / 32, INTER_D / 8), dim3(32, 8)>>>(w1, w16_1, INTER_D, HID);
    permute_w<<<dim3(HID / 32, INTER_D / 8), dim3(32, 8)>>>(w2, w16_2, INTER_D, HID);
    permute_w<<<dim3(OUT_DIM / 32, INTER_D / 8), dim3(32, 8)>>>(w3, w16_3, INTER_D, OUT_DIM);

    gate_kernel<<<B_ROWS / 8, 128>>>(z, c, g0w, g0b, g1w, g1b, g2w, g2b, coeff);

    // layer 0
    ln_scale_kernel<COND><<<B_ROWS / 8, 256>>>(z, c, coeff, a16);
    moe_gemm_h<KT0, HID, true><<<dim3(HID / 128, B_ROWS / 128), 128, GEMM_SMEM>>>(
        a16, coeff, w16_0, b0, hA);
    // layer 1
    ln_scale_kernel<HID><<<B_ROWS / 8, 256>>>(z, hA, coeff, a16);
    moe_gemm_h<KT1, HID, true><<<dim3(HID / 128, B_ROWS / 128), 128, GEMM_SMEM>>>(
        a16, coeff, w16_1, b1, hB);
    // layer 2
    ln_scale_kernel<HID><<<B_ROWS / 8, 256>>>(z, hB, coeff, a16);
    moe_gemm_h<KT1, HID, true><<<dim3(HID / 128, B_ROWS / 128), 128, GEMM_SMEM>>>(
        a16, coeff, w16_2, b2, hA);
    // layer 3 (no activation) -> d_out
    ln_scale_kernel<HID><<<B_ROWS / 8, 256>>>(z, hA, coeff, a16);
    moe_gemm_h<KT1, OUT_DIM, false><<<dim3(OUT_DIM / 128, B_ROWS / 128), 128, GEMM_SMEM>>>(
        a16, coeff, w16_3, b3, (float*)d_out);
}